// round 1
// baseline (speedup 1.0000x reference)
#include <cuda_runtime.h>
#include <math.h>

// ---------------- problem constants ----------------
#define NNODE 200
#define IMGF  2048
#define HD1   512
#define HD2   256
#define NCH   1024
#define NEDGE 39800
#define TE    32

// ---------------- device scratch (no allocs allowed) ----------------
__device__ float g_h1[NNODE * HD1];
__device__ float g_h2[NNODE * HD2];
__device__ float g_x[NNODE * NCH];
__device__ float g_wp2t[NCH * 512];   // permuted wp2: [i][k*4+o]
__device__ float g_M[NNODE * 512];    // M[n][k*4+o]
__device__ float g_c[NNODE * 4];
__device__ float g_attr[NNODE * 8];

// ---------------- tiny kernels ----------------
__global__ void k_attr(const float* __restrict__ bbox, const float* __restrict__ dir,
                       float* __restrict__ attr) {
    int t = blockIdx.x * 128 + threadIdx.x;
    if (t >= NNODE * 8) return;
    int n = t >> 3, c = t & 7;
    attr[t] = (c < 4) ? bbox[n * 4 + c] * (1.0f / 1024.0f) : dir[n * 4 + (c - 4)];
}

// g_wp2t[i*512 + (k*4+o)] = wp2[k*4096 + i*4 + o]
__global__ void k_tr(const float* __restrict__ wp2, float* __restrict__ wt) {
    int t = blockIdx.x * 256 + threadIdx.x;
    if (t >= NCH * 512) return;
    int i = t >> 9, j = t & 511;
    wt[t] = wp2[(j >> 2) * 4096 + (i << 2) + (j & 3)];
}

// explicit concepts / c-vector / root term : 3 x [200,4] reductions over 1024
__global__ void k_vec4(const float* __restrict__ x,
                       const float* __restrict__ wi, const float* __restrict__ bi,
                       const float* __restrict__ bp2,
                       const float* __restrict__ rw, const float* __restrict__ rb,
                       float* __restrict__ out_expl, float* __restrict__ cvec,
                       float* __restrict__ out_agg) {
    int t = blockIdx.x * 128 + threadIdx.x;
    if (t >= 3 * NNODE * 4) return;
    int mode = t / (NNODE * 4);
    int q = t % (NNODE * 4);
    int n = q >> 2, o = q & 3;
    const float* xr = x + n * NCH;
    const float* w = (mode == 0) ? wi : (mode == 1) ? bp2 : rw;
    float s = 0.f;
    #pragma unroll 8
    for (int i = 0; i < NCH; ++i) s += xr[i] * w[i * 4 + o];
    if (mode == 0)      out_expl[q] = 1.f / (1.f + expf(-(s + bi[o])));
    else if (mode == 1) cvec[q] = s;
    else                out_agg[q] = s + rb[o];
}

// ---------------- generic SGEMM: C[MxN] = A[MxK] @ B[KxN] (+bias, opt relu) ----------------
// BM=32, BN=64, BK=16, 256 threads, 2x4 micro-tile
template <int ACT>
__global__ void __launch_bounds__(256) sgemm(const float* __restrict__ A,
                                             const float* __restrict__ B,
                                             const float* __restrict__ bias,
                                             float* __restrict__ C,
                                             int M, int N, int K) {
    __shared__ float sA[16][33];
    __shared__ float sB[16][68];
    const int tid = threadIdx.x;
    const int tx = tid & 15, ty = tid >> 4;
    const int m0 = blockIdx.y * 32, n0 = blockIdx.x * 64;
    float acc[2][4] = {};
    for (int k0 = 0; k0 < K; k0 += 16) {
        if (tid < 128) {
            int m = tid >> 2, kq = (tid & 3) << 2;
            float4 a = make_float4(0.f, 0.f, 0.f, 0.f);
            if (m0 + m < M) a = *(const float4*)(A + (size_t)(m0 + m) * K + k0 + kq);
            sA[kq + 0][m] = a.x; sA[kq + 1][m] = a.y;
            sA[kq + 2][m] = a.z; sA[kq + 3][m] = a.w;
        }
        {
            int k = tid >> 4, n4 = (tid & 15) << 2;
            float4 b = *(const float4*)(B + (size_t)(k0 + k) * N + n0 + n4);
            *(float4*)&sB[k][n4] = b;
        }
        __syncthreads();
        #pragma unroll
        for (int k = 0; k < 16; ++k) {
            float a0 = sA[k][ty * 2 + 0];
            float a1 = sA[k][ty * 2 + 1];
            float4 b = *(const float4*)&sB[k][tx * 4];
            acc[0][0] += a0 * b.x; acc[0][1] += a0 * b.y;
            acc[0][2] += a0 * b.z; acc[0][3] += a0 * b.w;
            acc[1][0] += a1 * b.x; acc[1][1] += a1 * b.y;
            acc[1][2] += a1 * b.z; acc[1][3] += a1 * b.w;
        }
        __syncthreads();
    }
    #pragma unroll
    for (int i = 0; i < 2; ++i) {
        int row = m0 + ty * 2 + i;
        if (row >= M) continue;
        #pragma unroll
        for (int j = 0; j < 4; ++j) {
            int col = n0 + tx * 4 + j;
            float v = acc[i][j];
            if (bias) v += bias[col];
            if (ACT) v = fmaxf(v, 0.f);
            C[(size_t)row * N + col] = v;
        }
    }
}

// ---------------- fused edge pipeline ----------------
// per block: TE=32 edges, 128 threads.
// pair(16) -> relu(we1:16x256) -> relu(we2:256x64) -> sigmoid(we3:64x3) + hp
//   -> write edge_attr out
// -> h = relu(ea4 @ wp1:4x128) -> msg[o] = c[src,o] + sum_k h[k]*M[src,k*4+o]
//   -> atomicAdd agg[dst]
__global__ void __launch_bounds__(128) k_edge(
    const float* __restrict__ attr, const float* __restrict__ pri,
    const float* __restrict__ we1, const float* __restrict__ be1,
    const float* __restrict__ we2, const float* __restrict__ be2,
    const float* __restrict__ we3, const float* __restrict__ be3,
    const float* __restrict__ wp1, const float* __restrict__ bp1,
    const float* __restrict__ Mn, const float* __restrict__ cvec,
    float* __restrict__ out_ea, float* __restrict__ out_agg) {
    __shared__ float s_pair[TE][17];
    __shared__ float s_big[TE * 264];   // h1 [e][256(+pad)] ; reused later as h [e][132]
    __shared__ float s_h2[TE][68];
    __shared__ float s_ea[TE][4];
    __shared__ int s_src[TE], s_dst[TE];

    const int t = threadIdx.x;
    const int e0 = blockIdx.x * TE;

    if (t < TE) {
        int e = e0 + t;
        if (e >= NEDGE) e = NEDGE - 1;
        int i = e / 199;
        int r = e - i * 199;
        int j = (r < i) ? r : (r + 1);
        s_src[t] = i;
        s_dst[t] = j;
    }
    __syncthreads();

    // pair features: [src attr(8), dst attr(8)]
    #pragma unroll
    for (int l = 0; l < 4; ++l) {
        int q = t + l * 128;
        int el = q >> 4, c = q & 15;
        int node = (c < 8) ? s_src[el] : s_dst[el];
        s_pair[el][c] = attr[node * 8 + (c & 7)];
    }
    __syncthreads();

    const int eg = t >> 4, cg = t & 15;   // eg<8 (4 edges each), cg<16 (col groups)

    // ---- phase 1: L1 16->256, thread computes 4 edges x 16 cols (two 8-col halves)
    #pragma unroll
    for (int half = 0; half < 2; ++half) {
        float acc[4][8] = {};
        #pragma unroll
        for (int j = 0; j < 16; ++j) {
            float pa0 = s_pair[eg * 4 + 0][j];
            float pa1 = s_pair[eg * 4 + 1][j];
            float pa2 = s_pair[eg * 4 + 2][j];
            float pa3 = s_pair[eg * 4 + 3][j];
            const float4* wr = (const float4*)(we1 + j * 256 + cg * 16 + half * 8);
            float4 w0 = wr[0], w1 = wr[1];
            float wv[8] = {w0.x, w0.y, w0.z, w0.w, w1.x, w1.y, w1.z, w1.w};
            #pragma unroll
            for (int c = 0; c < 8; ++c) {
                acc[0][c] += pa0 * wv[c];
                acc[1][c] += pa1 * wv[c];
                acc[2][c] += pa2 * wv[c];
                acc[3][c] += pa3 * wv[c];
            }
        }
        int colb = cg * 16 + half * 8;
        #pragma unroll
        for (int i2 = 0; i2 < 4; ++i2) {
            float o0 = fmaxf(acc[i2][0] + be1[colb + 0], 0.f);
            float o1 = fmaxf(acc[i2][1] + be1[colb + 1], 0.f);
            float o2 = fmaxf(acc[i2][2] + be1[colb + 2], 0.f);
            float o3 = fmaxf(acc[i2][3] + be1[colb + 3], 0.f);
            float o4 = fmaxf(acc[i2][4] + be1[colb + 4], 0.f);
            float o5 = fmaxf(acc[i2][5] + be1[colb + 5], 0.f);
            float o6 = fmaxf(acc[i2][6] + be1[colb + 6], 0.f);
            float o7 = fmaxf(acc[i2][7] + be1[colb + 7], 0.f);
            float* row = &s_big[(eg * 4 + i2) * 264 + colb];
            *(float4*)(row + 0) = make_float4(o0, o1, o2, o3);
            *(float4*)(row + 4) = make_float4(o4, o5, o6, o7);
        }
    }
    __syncthreads();

    // ---- phase 2: L2 256->64, thread computes 4 edges x 4 cols
    {
        float acc[4][4] = {};
        const float4* we2v = (const float4*)we2;
        #pragma unroll 8
        for (int k = 0; k < 256; ++k) {
            float a0 = s_big[(eg * 4 + 0) * 264 + k];
            float a1 = s_big[(eg * 4 + 1) * 264 + k];
            float a2 = s_big[(eg * 4 + 2) * 264 + k];
            float a3 = s_big[(eg * 4 + 3) * 264 + k];
            float4 b = we2v[k * 16 + cg];
            acc[0][0] += a0 * b.x; acc[0][1] += a0 * b.y; acc[0][2] += a0 * b.z; acc[0][3] += a0 * b.w;
            acc[1][0] += a1 * b.x; acc[1][1] += a1 * b.y; acc[1][2] += a1 * b.z; acc[1][3] += a1 * b.w;
            acc[2][0] += a2 * b.x; acc[2][1] += a2 * b.y; acc[2][2] += a2 * b.z; acc[2][3] += a2 * b.w;
            acc[3][0] += a3 * b.x; acc[3][1] += a3 * b.y; acc[3][2] += a3 * b.z; acc[3][3] += a3 * b.w;
        }
        #pragma unroll
        for (int i2 = 0; i2 < 4; ++i2) {
            int e = eg * 4 + i2;
            #pragma unroll
            for (int j = 0; j < 4; ++j)
                s_h2[e][cg * 4 + j] = fmaxf(acc[i2][j] + be2[cg * 4 + j], 0.f);
        }
    }
    __syncthreads();

    // ---- phase 3: L3 64->3 + sigmoid, plus higher-priority bit
    if (t < 96) {
        int e = t / 3, c = t - (t / 3) * 3;
        float s = be3[c];
        #pragma unroll 8
        for (int k = 0; k < 64; ++k) s += s_h2[e][k] * we3[k * 3 + c];
        s_ea[e][c] = 1.f / (1.f + expf(-s));
    }
    if (t < TE) {
        s_ea[t][3] = (pri[s_src[t]] > pri[s_dst[t]]) ? 1.f : 0.f;
    }
    __syncthreads();

    // write edge attributes output
    {
        int e = t >> 2, c = t & 3;
        if (e0 + e < NEDGE) out_ea[(size_t)(e0 + e) * 4 + c] = s_ea[e][c];
    }

    // ---- phase 4: h = relu(ea4 @ wp1 + bp1), 4->128 ; reuse s_big as h[e][132]
    float* s_h = s_big;
    {
        int e = t >> 2, kg = t & 3;
        float q0 = s_ea[e][0], q1 = s_ea[e][1], q2 = s_ea[e][2], q3 = s_ea[e][3];
        #pragma unroll 8
        for (int kk = 0; kk < 32; ++kk) {
            int k = kg * 32 + kk;
            float v = bp1[k] + q0 * wp1[k] + q1 * wp1[128 + k]
                             + q2 * wp1[256 + k] + q3 * wp1[384 + k];
            s_h[e * 132 + k] = fmaxf(v, 0.f);
        }
    }
    __syncthreads();

    // ---- phase 5: msg + scatter-add (1 thread per edge)
    if (t < TE) {
        int e = t;
        int src = s_src[e], dst = s_dst[e];
        const float4* Mv = (const float4*)(Mn + src * 512);
        float4 a = *(const float4*)(cvec + src * 4);
        #pragma unroll 8
        for (int k = 0; k < 128; ++k) {
            float h = s_h[e * 132 + k];
            float4 m = Mv[k];
            a.x += h * m.x; a.y += h * m.y; a.z += h * m.z; a.w += h * m.w;
        }
        if (e0 + e < NEDGE) {
            atomicAdd(&out_agg[dst * 4 + 0], a.x);
            atomicAdd(&out_agg[dst * 4 + 1], a.y);
            atomicAdd(&out_agg[dst * 4 + 2], a.z);
            atomicAdd(&out_agg[dst * 4 + 3], a.w);
        }
    }
}

// ---------------- launch ----------------
extern "C" void kernel_launch(void* const* d_in, const int* in_sizes, int n_in,
                              void* d_out, int out_size) {
    const float* roi  = (const float*)d_in[0];   // [2,200,2048] (batch 0 = first 200*2048)
    const float* bbox = (const float*)d_in[1];
    const float* dir  = (const float*)d_in[2];
    const float* pri  = (const float*)d_in[3];
    const float* w1  = (const float*)d_in[4];  const float* b1  = (const float*)d_in[5];
    const float* w2  = (const float*)d_in[6];  const float* b2  = (const float*)d_in[7];
    const float* w3  = (const float*)d_in[8];  const float* b3  = (const float*)d_in[9];
    const float* wi  = (const float*)d_in[10]; const float* bi  = (const float*)d_in[11];
    const float* we1 = (const float*)d_in[12]; const float* be1 = (const float*)d_in[13];
    const float* we2 = (const float*)d_in[14]; const float* be2 = (const float*)d_in[15];
    const float* we3 = (const float*)d_in[16]; const float* be3 = (const float*)d_in[17];
    const float* wp1 = (const float*)d_in[18]; const float* bp1 = (const float*)d_in[19];
    const float* wp2 = (const float*)d_in[20]; const float* bp2 = (const float*)d_in[21];
    const float* rw  = (const float*)d_in[22]; const float* rb  = (const float*)d_in[23];
    float* out = (float*)d_out;   // [0,800) next_actions | [800,1600) explicit | [1600,..) edge attrs

    float *p_h1, *p_h2, *p_x, *p_wt, *p_M, *p_c, *p_attr;
    cudaGetSymbolAddress((void**)&p_h1,  g_h1);
    cudaGetSymbolAddress((void**)&p_h2,  g_h2);
    cudaGetSymbolAddress((void**)&p_x,   g_x);
    cudaGetSymbolAddress((void**)&p_wt,  g_wp2t);
    cudaGetSymbolAddress((void**)&p_M,   g_M);
    cudaGetSymbolAddress((void**)&p_c,   g_c);
    cudaGetSymbolAddress((void**)&p_attr, g_attr);

    k_attr<<<(NNODE * 8 + 127) / 128, 128>>>(bbox, dir, p_attr);
    k_tr<<<(NCH * 512) / 256, 256>>>(wp2, p_wt);

    // node MLP (batch 0 only)
    sgemm<1><<<dim3(HD1 / 64, 7), 256>>>(roi, w1, b1, p_h1, NNODE, HD1, IMGF);
    sgemm<1><<<dim3(HD2 / 64, 7), 256>>>(p_h1, w2, b2, p_h2, NNODE, HD2, HD1);
    sgemm<0><<<dim3(NCH / 64, 7), 256>>>(p_h2, w3, b3, p_x, NNODE, NCH, HD2);

    // M[n, k*4+o] = x @ wp2t   (NNConv factorization)
    sgemm<0><<<dim3(512 / 64, 7), 256>>>(p_x, p_wt, (const float*)nullptr, p_M,
                                         NNODE, 512, NCH);

    // explicit concepts -> out+800 ; c vector ; root term -> out[0,800)
    k_vec4<<<(3 * NNODE * 4 + 127) / 128, 128>>>(p_x, wi, bi, bp2, rw, rb,
                                                 out + 800, p_c, out);

    // fused edge pipeline
    k_edge<<<(NEDGE + TE - 1) / TE, 128>>>(p_attr, pri,
                                           we1, be1, we2, be2, we3, be3,
                                           wp1, bp1, p_M, p_c,
                                           out + 1600, out);
}

// round 2
// speedup vs baseline: 2.4133x; 2.4133x over previous
#include <cuda_runtime.h>
#include <math.h>

typedef unsigned long long ull;

// ---------------- problem constants ----------------
#define NNODE 200
#define IMGF  2048
#define HD1   512
#define HD2   256
#define NCH   1024
#define NEDGE 39800
#define TE    32

// ---------------- f32x2 helpers (packed dual-FMA, PTX-only on sm_103a) ---------
__device__ __forceinline__ ull pack2(float a) {
    ull r; asm("mov.b64 %0,{%1,%1};" : "=l"(r) : "f"(a)); return r;
}
__device__ __forceinline__ void ffma2(ull& acc, ull a, ull b) {
    asm("fma.rn.f32x2 %0,%1,%2,%0;" : "+l"(acc) : "l"(a), "l"(b));
}
__device__ __forceinline__ float2 unpk(ull v) {
    float2 r; asm("mov.b64 {%0,%1},%2;" : "=f"(r.x), "=f"(r.y) : "l"(v)); return r;
}

// ---------------- device scratch (single block, one memset) ----------------
#define OFF_H1 0
#define OFF_H2 (OFF_H1 + NNODE*HD1)
#define OFF_X  (OFF_H2 + NNODE*HD2)
#define OFF_M  (OFF_X  + NNODE*NCH)
#define ZERO_CNT (OFF_M + NNODE*512)          // h1,h2,x,M zero-initialized
#define OFF_WT (ZERO_CNT)
#define OFF_C  (OFF_WT + NCH*512)
#define OFF_AT (OFF_C + NNODE*4)
#define SCR_TOTAL (OFF_AT + NNODE*8)
__device__ float g_scr[SCR_TOTAL];

// ---------------- tiny kernels ----------------
__global__ void k_attr(const float* __restrict__ bbox, const float* __restrict__ dir,
                       float* __restrict__ attr) {
    int t = blockIdx.x * 128 + threadIdx.x;
    if (t >= NNODE * 8) return;
    int n = t >> 3, c = t & 7;
    attr[t] = (c < 4) ? bbox[n * 4 + c] * (1.0f / 1024.0f) : dir[n * 4 + (c - 4)];
}

// wt[i][k*4+o] = wp2[k][i*4+o] : float4-granular transpose, coalesced reads
__global__ void k_tr(const float* __restrict__ wp2, float* __restrict__ wt) {
    int t = blockIdx.x * 256 + threadIdx.x;
    if (t >= 128 * 1024) return;
    int k = t >> 10, i = t & 1023;
    float4 v = ((const float4*)wp2)[t];
    ((float4*)wt)[i * 128 + k] = v;
}

// per-node [1024] -> 12 outputs: explicit concepts, c-vector, root term
__global__ void __launch_bounds__(256) k_vec4b(
    const float* __restrict__ x,
    const float* __restrict__ wi, const float* __restrict__ bi,
    const float* __restrict__ bp2,
    const float* __restrict__ rw, const float* __restrict__ rb,
    float* __restrict__ out_expl, float* __restrict__ cvec,
    float* __restrict__ out_agg) {
    int n = blockIdx.x, t = threadIdx.x;
    float4 xv = *(const float4*)(x + (size_t)n * NCH + t * 4);
    float xa[4] = {xv.x, xv.y, xv.z, xv.w};
    float v[12];
    #pragma unroll
    for (int c = 0; c < 12; ++c) v[c] = 0.f;
    #pragma unroll
    for (int j = 0; j < 4; ++j) {
        int i = t * 4 + j;
        float xs = xa[j];
        float4 w0 = *(const float4*)(wi  + i * 4);
        float4 w1 = *(const float4*)(bp2 + i * 4);
        float4 w2 = *(const float4*)(rw  + i * 4);
        v[0] += xs * w0.x; v[1] += xs * w0.y; v[2]  += xs * w0.z; v[3]  += xs * w0.w;
        v[4] += xs * w1.x; v[5] += xs * w1.y; v[6]  += xs * w1.z; v[7]  += xs * w1.w;
        v[8] += xs * w2.x; v[9] += xs * w2.y; v[10] += xs * w2.z; v[11] += xs * w2.w;
    }
    #pragma unroll
    for (int s = 16; s; s >>= 1)
        #pragma unroll
        for (int c = 0; c < 12; ++c) v[c] += __shfl_xor_sync(0xffffffffu, v[c], s);
    __shared__ float red[8][12];
    if ((t & 31) == 0)
        #pragma unroll
        for (int c = 0; c < 12; ++c) red[t >> 5][c] = v[c];
    __syncthreads();
    if (t < 12) {
        float s = 0.f;
        #pragma unroll
        for (int w = 0; w < 8; ++w) s += red[w][t];
        int o = t & 3;
        if (t < 4)       out_expl[n * 4 + o] = 1.f / (1.f + __expf(-(s + bi[o])));
        else if (t < 8)  cvec[n * 4 + o] = s;
        else             out_agg[n * 4 + o] = s + rb[o];
    }
}

// ---------------- split-K SGEMM: atomicAdd(C, A@B), split 0 adds bias --------
// BM=32, BN=128, BK=16, 256 threads, 4x4 micro-tile with f32x2.
// RELU_A: apply relu to A elements at load (previous layer's activation).
template <int RELU_A>
__global__ void __launch_bounds__(256) sgemm_sk(
    const float* __restrict__ A, const float* __restrict__ B,
    const float* __restrict__ bias, float* __restrict__ C,
    int M, int N, int K, int Ks) {
    __shared__ float sA[16][36];
    __shared__ float sB[16][132];
    const int tid = threadIdx.x;
    const int tx = tid & 31, ty = tid >> 5;
    const int m0 = blockIdx.y * 32, n0 = blockIdx.x * 128;
    const int kbeg = blockIdx.z * Ks;
    ull acc[8];
    #pragma unroll
    for (int i = 0; i < 8; ++i) acc[i] = 0ULL;

    for (int k0 = kbeg; k0 < kbeg + Ks; k0 += 16) {
        {   // A tile: 32 rows x 16 k
            int m = tid >> 3, kq = (tid & 7) * 2;
            float2 a = make_float2(0.f, 0.f);
            if (m0 + m < M) a = *(const float2*)(A + (size_t)(m0 + m) * K + k0 + kq);
            if (RELU_A) { a.x = fmaxf(a.x, 0.f); a.y = fmaxf(a.y, 0.f); }
            sA[kq][m] = a.x; sA[kq + 1][m] = a.y;
        }
        {   // B tile: 16 k x 128 n
            int k = tid >> 4, n8 = (tid & 15) * 8;
            const float* bp = B + (size_t)(k0 + k) * N + n0 + n8;
            float4 b0 = *(const float4*)(bp);
            float4 b1 = *(const float4*)(bp + 4);
            *(float4*)&sB[k][n8] = b0;
            *(float4*)&sB[k][n8 + 4] = b1;
        }
        __syncthreads();
        #pragma unroll
        for (int k = 0; k < 16; ++k) {
            float4 av = *(const float4*)&sA[k][ty * 4];
            ulonglong2 bv = *(const ulonglong2*)&sB[k][tx * 4];
            ull a0 = pack2(av.x), a1 = pack2(av.y), a2 = pack2(av.z), a3 = pack2(av.w);
            ffma2(acc[0], a0, bv.x); ffma2(acc[1], a0, bv.y);
            ffma2(acc[2], a1, bv.x); ffma2(acc[3], a1, bv.y);
            ffma2(acc[4], a2, bv.x); ffma2(acc[5], a2, bv.y);
            ffma2(acc[6], a3, bv.x); ffma2(acc[7], a3, bv.y);
        }
        __syncthreads();
    }
    const bool addb = (bias != nullptr) && (blockIdx.z == 0);
    #pragma unroll
    for (int r = 0; r < 4; ++r) {
        int row = m0 + ty * 4 + r;
        if (row >= M) continue;
        float2 v01 = unpk(acc[r * 2]), v23 = unpk(acc[r * 2 + 1]);
        float v[4] = {v01.x, v01.y, v23.x, v23.y};
        int col = n0 + tx * 4;
        #pragma unroll
        for (int j = 0; j < 4; ++j) {
            float o = v[j];
            if (addb) o += bias[col + j];
            atomicAdd(&C[(size_t)row * N + col + j], o);
        }
    }
}

// ---------------- fused edge pipeline ----------------
__global__ void __launch_bounds__(128) k_edge(
    const float* __restrict__ attr, const float* __restrict__ pri,
    const float* __restrict__ we1, const float* __restrict__ be1,
    const float* __restrict__ we2, const float* __restrict__ be2,
    const float* __restrict__ we3, const float* __restrict__ be3,
    const float* __restrict__ wp1, const float* __restrict__ bp1,
    const float* __restrict__ Mn, const float* __restrict__ cvec,
    float* __restrict__ out_ea, float* __restrict__ out_agg) {
    __shared__ float s_pair[TE][17];
    __shared__ float s_big[TE * 264];   // h1 [e][256(+8)] ; later reused as h [e][132]
    __shared__ float s_h2[TE][68];
    __shared__ float s_ea[TE][4];
    __shared__ int s_src[TE], s_dst[TE];

    const int t = threadIdx.x;
    const int e0 = blockIdx.x * TE;

    if (t < TE) {
        int e = e0 + t;
        if (e >= NEDGE) e = NEDGE - 1;
        int i = e / 199;
        int r = e - i * 199;
        int j = (r < i) ? r : (r + 1);
        s_src[t] = i; s_dst[t] = j;
    }
    __syncthreads();

    #pragma unroll
    for (int l = 0; l < 4; ++l) {
        int q = t + l * 128;
        int el = q >> 4, c = q & 15;
        int node = (c < 8) ? s_src[el] : s_dst[el];
        s_pair[el][c] = attr[node * 8 + (c & 7)];
    }
    __syncthreads();

    const int eg = t >> 4, cg = t & 15;

    // ---- phase 1: L1 16->256 (f32x2): 4 edges x 16 cols per thread
    #pragma unroll
    for (int half = 0; half < 2; ++half) {
        ull acc2[4][4];
        #pragma unroll
        for (int e = 0; e < 4; ++e)
            #pragma unroll
            for (int p = 0; p < 4; ++p) acc2[e][p] = 0ULL;
        #pragma unroll
        for (int j = 0; j < 16; ++j) {
            const ulonglong2* wr = (const ulonglong2*)(we1 + j * 256 + cg * 16 + half * 8);
            ulonglong2 w01 = wr[0], w23 = wr[1];
            #pragma unroll
            for (int e = 0; e < 4; ++e) {
                ull pa = pack2(s_pair[eg * 4 + e][j]);
                ffma2(acc2[e][0], pa, w01.x);
                ffma2(acc2[e][1], pa, w01.y);
                ffma2(acc2[e][2], pa, w23.x);
                ffma2(acc2[e][3], pa, w23.y);
            }
        }
        int colb = cg * 16 + half * 8;
        #pragma unroll
        for (int e = 0; e < 4; ++e) {
            float o[8];
            #pragma unroll
            for (int p = 0; p < 4; ++p) {
                float2 u = unpk(acc2[e][p]);
                o[p * 2] = u.x; o[p * 2 + 1] = u.y;
            }
            #pragma unroll
            for (int c = 0; c < 8; ++c) o[c] = fmaxf(o[c] + be1[colb + c], 0.f);
            float* row = &s_big[(eg * 4 + e) * 264 + colb];
            *(float4*)(row + 0) = make_float4(o[0], o[1], o[2], o[3]);
            *(float4*)(row + 4) = make_float4(o[4], o[5], o[6], o[7]);
        }
    }
    __syncthreads();

    // ---- phase 2: L2 256->64 (f32x2): 4 edges x 4 cols per thread
    {
        ull acc01[4], acc23[4];
        #pragma unroll
        for (int e = 0; e < 4; ++e) { acc01[e] = 0ULL; acc23[e] = 0ULL; }
        #pragma unroll 8
        for (int k = 0; k < 256; ++k) {
            float a0 = s_big[(eg * 4 + 0) * 264 + k];
            float a1 = s_big[(eg * 4 + 1) * 264 + k];
            float a2 = s_big[(eg * 4 + 2) * 264 + k];
            float a3 = s_big[(eg * 4 + 3) * 264 + k];
            ulonglong2 b = *(const ulonglong2*)(we2 + k * 64 + cg * 4);
            ull p0 = pack2(a0), p1 = pack2(a1), p2 = pack2(a2), p3 = pack2(a3);
            ffma2(acc01[0], p0, b.x); ffma2(acc23[0], p0, b.y);
            ffma2(acc01[1], p1, b.x); ffma2(acc23[1], p1, b.y);
            ffma2(acc01[2], p2, b.x); ffma2(acc23[2], p2, b.y);
            ffma2(acc01[3], p3, b.x); ffma2(acc23[3], p3, b.y);
        }
        #pragma unroll
        for (int e = 0; e < 4; ++e) {
            float2 u0 = unpk(acc01[e]), u1 = unpk(acc23[e]);
            s_h2[eg * 4 + e][cg * 4 + 0] = fmaxf(u0.x + be2[cg * 4 + 0], 0.f);
            s_h2[eg * 4 + e][cg * 4 + 1] = fmaxf(u0.y + be2[cg * 4 + 1], 0.f);
            s_h2[eg * 4 + e][cg * 4 + 2] = fmaxf(u1.x + be2[cg * 4 + 2], 0.f);
            s_h2[eg * 4 + e][cg * 4 + 3] = fmaxf(u1.y + be2[cg * 4 + 3], 0.f);
        }
    }
    __syncthreads();

    // ---- phase 3: L3 64->3 + sigmoid, plus higher-priority bit
    if (t < 96) {
        int e = t / 3, c = t - (t / 3) * 3;
        float s = be3[c];
        #pragma unroll 8
        for (int k = 0; k < 64; ++k) s += s_h2[e][k] * we3[k * 3 + c];
        s_ea[e][c] = 1.f / (1.f + __expf(-s));
    }
    if (t < TE) s_ea[t][3] = (pri[s_src[t]] > pri[s_dst[t]]) ? 1.f : 0.f;
    __syncthreads();

    {   // write edge attributes
        int e = t >> 2, c = t & 3;
        if (e0 + e < NEDGE) out_ea[(size_t)(e0 + e) * 4 + c] = s_ea[e][c];
    }

    // ---- phase 4: h = relu(ea4 @ wp1 + bp1), 4->128 ; reuse s_big as h[e][132]
    float* s_h = s_big;
    {
        int e = t >> 2, kg = t & 3;
        float q0 = s_ea[e][0], q1 = s_ea[e][1], q2 = s_ea[e][2], q3 = s_ea[e][3];
        #pragma unroll 8
        for (int kk = 0; kk < 32; ++kk) {
            int k = kg * 32 + kk;
            float v = bp1[k] + q0 * wp1[k] + q1 * wp1[128 + k]
                             + q2 * wp1[256 + k] + q3 * wp1[384 + k];
            s_h[e * 132 + k] = fmaxf(v, 0.f);
        }
    }
    __syncthreads();

    // ---- phase 5: msg + scatter-add, all 128 threads (4 per edge) + shfl reduce
    {
        int e = t >> 2, q = t & 3;
        int src = s_src[e], dst = s_dst[e];
        const float4* Mv = (const float4*)(Mn + src * 512);
        float4 a = make_float4(0.f, 0.f, 0.f, 0.f);
        #pragma unroll 8
        for (int kk = 0; kk < 32; ++kk) {
            int k = q * 32 + kk;
            float h = s_h[e * 132 + k];
            float4 m = Mv[k];
            a.x += h * m.x; a.y += h * m.y; a.z += h * m.z; a.w += h * m.w;
        }
        #pragma unroll
        for (int s = 1; s < 4; s <<= 1) {
            a.x += __shfl_xor_sync(0xffffffffu, a.x, s);
            a.y += __shfl_xor_sync(0xffffffffu, a.y, s);
            a.z += __shfl_xor_sync(0xffffffffu, a.z, s);
            a.w += __shfl_xor_sync(0xffffffffu, a.w, s);
        }
        if (q == 0 && e0 + e < NEDGE) {
            float4 cv = *(const float4*)(cvec + src * 4);
            atomicAdd(&out_agg[dst * 4 + 0], a.x + cv.x);
            atomicAdd(&out_agg[dst * 4 + 1], a.y + cv.y);
            atomicAdd(&out_agg[dst * 4 + 2], a.z + cv.z);
            atomicAdd(&out_agg[dst * 4 + 3], a.w + cv.w);
        }
    }
}

// ---------------- launch ----------------
extern "C" void kernel_launch(void* const* d_in, const int* in_sizes, int n_in,
                              void* d_out, int out_size) {
    const float* roi  = (const float*)d_in[0];
    const float* bbox = (const float*)d_in[1];
    const float* dir  = (const float*)d_in[2];
    const float* pri  = (const float*)d_in[3];
    const float* w1  = (const float*)d_in[4];  const float* b1  = (const float*)d_in[5];
    const float* w2  = (const float*)d_in[6];  const float* b2  = (const float*)d_in[7];
    const float* w3  = (const float*)d_in[8];  const float* b3  = (const float*)d_in[9];
    const float* wi  = (const float*)d_in[10]; const float* bi  = (const float*)d_in[11];
    const float* we1 = (const float*)d_in[12]; const float* be1 = (const float*)d_in[13];
    const float* we2 = (const float*)d_in[14]; const float* be2 = (const float*)d_in[15];
    const float* we3 = (const float*)d_in[16]; const float* be3 = (const float*)d_in[17];
    const float* wp1 = (const float*)d_in[18]; const float* bp1 = (const float*)d_in[19];
    const float* wp2 = (const float*)d_in[20]; const float* bp2 = (const float*)d_in[21];
    const float* rw  = (const float*)d_in[22]; const float* rb  = (const float*)d_in[23];
    float* out = (float*)d_out;

    float* scr;
    cudaGetSymbolAddress((void**)&scr, g_scr);
    float* p_h1 = scr + OFF_H1;
    float* p_h2 = scr + OFF_H2;
    float* p_x  = scr + OFF_X;
    float* p_M  = scr + OFF_M;
    float* p_wt = scr + OFF_WT;
    float* p_c  = scr + OFF_C;
    float* p_at = scr + OFF_AT;

    cudaMemsetAsync(scr, 0, ZERO_CNT * sizeof(float));

    k_attr<<<(NNODE * 8 + 127) / 128, 128>>>(bbox, dir, p_at);
    k_tr<<<(128 * 1024) / 256, 256>>>(wp2, p_wt);

    // node MLP (batch 0 only), split-K, bias by split 0, relu folded into consumer
    sgemm_sk<0><<<dim3(4, 7, 8), 256>>>(roi,  w1, b1, p_h1, NNODE, HD1, IMGF, 256);
    sgemm_sk<1><<<dim3(2, 7, 8), 256>>>(p_h1, w2, b2, p_h2, NNODE, HD2, HD1,  64);
    sgemm_sk<1><<<dim3(8, 7, 4), 256>>>(p_h2, w3, b3, p_x,  NNODE, NCH, HD2,  64);

    // M[n, k*4+o] = x @ wp2t  (x already includes b3 -> exact)
    sgemm_sk<0><<<dim3(4, 7, 8), 256>>>(p_x, p_wt, (const float*)nullptr, p_M,
                                        NNODE, 512, NCH, 128);

    k_vec4b<<<NNODE, 256>>>(p_x, wi, bi, bp2, rw, rb, out + 800, p_c, out);

    k_edge<<<(NEDGE + TE - 1) / TE, 128>>>(p_at, pri,
                                           we1, be1, we2, be2, we3, be3,
                                           wp1, bp1, p_M, p_c,
                                           out + 1600, out);
}

// round 3
// speedup vs baseline: 2.5959x; 1.0757x over previous
#include <cuda_runtime.h>
#include <math.h>

typedef unsigned long long ull;

// ---------------- problem constants ----------------
#define NNODE 200
#define IMGF  2048
#define HD1   512
#define HD2   256
#define NCH   1024
#define NEDGE 39800
#define TE    32

// ---------------- f32x2 helpers ----------------
__device__ __forceinline__ ull pack2(float a) {
    ull r; asm("mov.b64 %0,{%1,%1};" : "=l"(r) : "f"(a)); return r;
}
__device__ __forceinline__ void ffma2(ull& acc, ull a, ull b) {
    asm("fma.rn.f32x2 %0,%1,%2,%0;" : "+l"(acc) : "l"(a), "l"(b));
}
__device__ __forceinline__ float2 unpk(ull v) {
    float2 r; asm("mov.b64 {%0,%1},%2;" : "=f"(r.x), "=f"(r.y) : "l"(v)); return r;
}

// ---------------- device scratch ----------------
#define OFF_H1 0
#define OFF_H2 (OFF_H1 + NNODE*HD1)
#define OFF_X  (OFF_H2 + NNODE*HD2)
#define OFF_M  (OFF_X  + NNODE*NCH)
#define ZERO_CNT (OFF_M + NNODE*512)
#define OFF_WT (ZERO_CNT)
#define OFF_C  (OFF_WT + NCH*512)
#define SCR_TOTAL (OFF_C + NNODE*4)
__device__ float g_scr[SCR_TOTAL];

// wt[i][k*4+o] = wp2[k][i*4+o] : float4-granular transpose
__global__ void k_tr(const float* __restrict__ wp2, float* __restrict__ wt) {
    int t = blockIdx.x * 256 + threadIdx.x;
    if (t >= 128 * 1024) return;
    int k = t >> 10, i = t & 1023;
    float4 v = ((const float4*)wp2)[t];
    ((float4*)wt)[i * 128 + k] = v;
}

// per-node [1024] -> 12 outputs: explicit concepts, c-vector, root term
__global__ void __launch_bounds__(256) k_vec4b(
    const float* __restrict__ x,
    const float* __restrict__ wi, const float* __restrict__ bi,
    const float* __restrict__ bp2,
    const float* __restrict__ rw, const float* __restrict__ rb,
    float* __restrict__ out_expl, float* __restrict__ cvec,
    float* __restrict__ out_agg) {
    int n = blockIdx.x, t = threadIdx.x;
    float4 xv = *(const float4*)(x + (size_t)n * NCH + t * 4);
    float xa[4] = {xv.x, xv.y, xv.z, xv.w};
    float v[12];
    #pragma unroll
    for (int c = 0; c < 12; ++c) v[c] = 0.f;
    #pragma unroll
    for (int j = 0; j < 4; ++j) {
        int i = t * 4 + j;
        float xs = xa[j];
        float4 w0 = *(const float4*)(wi  + i * 4);
        float4 w1 = *(const float4*)(bp2 + i * 4);
        float4 w2 = *(const float4*)(rw  + i * 4);
        v[0] += xs * w0.x; v[1] += xs * w0.y; v[2]  += xs * w0.z; v[3]  += xs * w0.w;
        v[4] += xs * w1.x; v[5] += xs * w1.y; v[6]  += xs * w1.z; v[7]  += xs * w1.w;
        v[8] += xs * w2.x; v[9] += xs * w2.y; v[10] += xs * w2.z; v[11] += xs * w2.w;
    }
    #pragma unroll
    for (int s = 16; s; s >>= 1)
        #pragma unroll
        for (int c = 0; c < 12; ++c) v[c] += __shfl_xor_sync(0xffffffffu, v[c], s);
    __shared__ float red[8][12];
    if ((t & 31) == 0)
        #pragma unroll
        for (int c = 0; c < 12; ++c) red[t >> 5][c] = v[c];
    __syncthreads();
    if (t < 12) {
        float s = 0.f;
        #pragma unroll
        for (int w = 0; w < 8; ++w) s += red[w][t];
        int o = t & 3;
        if (t < 4)       out_expl[n * 4 + o] = 1.f / (1.f + __expf(-(s + bi[o])));
        else if (t < 8)  cvec[n * 4 + o] = s;
        else             out_agg[n * 4 + o] = s + rb[o];
    }
}

// ---------------- split-K SGEMM: atomicAdd(C, A@B), split 0 adds bias --------
template <int RELU_A>
__global__ void __launch_bounds__(256) sgemm_sk(
    const float* __restrict__ A, const float* __restrict__ B,
    const float* __restrict__ bias, float* __restrict__ C,
    int M, int N, int K, int Ks) {
    __shared__ float sA[16][36];
    __shared__ float sB[16][132];
    const int tid = threadIdx.x;
    const int tx = tid & 31, ty = tid >> 5;
    const int m0 = blockIdx.y * 32, n0 = blockIdx.x * 128;
    const int kbeg = blockIdx.z * Ks;
    ull acc[8];
    #pragma unroll
    for (int i = 0; i < 8; ++i) acc[i] = 0ULL;

    for (int k0 = kbeg; k0 < kbeg + Ks; k0 += 16) {
        {
            int m = tid >> 3, kq = (tid & 7) * 2;
            float2 a = make_float2(0.f, 0.f);
            if (m0 + m < M) a = *(const float2*)(A + (size_t)(m0 + m) * K + k0 + kq);
            if (RELU_A) { a.x = fmaxf(a.x, 0.f); a.y = fmaxf(a.y, 0.f); }
            sA[kq][m] = a.x; sA[kq + 1][m] = a.y;
        }
        {
            int k = tid >> 4, n8 = (tid & 15) * 8;
            const float* bp = B + (size_t)(k0 + k) * N + n0 + n8;
            float4 b0 = *(const float4*)(bp);
            float4 b1 = *(const float4*)(bp + 4);
            *(float4*)&sB[k][n8] = b0;
            *(float4*)&sB[k][n8 + 4] = b1;
        }
        __syncthreads();
        #pragma unroll
        for (int k = 0; k < 16; ++k) {
            float4 av = *(const float4*)&sA[k][ty * 4];
            ulonglong2 bv = *(const ulonglong2*)&sB[k][tx * 4];
            ull a0 = pack2(av.x), a1 = pack2(av.y), a2 = pack2(av.z), a3 = pack2(av.w);
            ffma2(acc[0], a0, bv.x); ffma2(acc[1], a0, bv.y);
            ffma2(acc[2], a1, bv.x); ffma2(acc[3], a1, bv.y);
            ffma2(acc[4], a2, bv.x); ffma2(acc[5], a2, bv.y);
            ffma2(acc[6], a3, bv.x); ffma2(acc[7], a3, bv.y);
        }
        __syncthreads();
    }
    const bool addb = (bias != nullptr) && (blockIdx.z == 0);
    #pragma unroll
    for (int r = 0; r < 4; ++r) {
        int row = m0 + ty * 4 + r;
        if (row >= M) continue;
        float2 v01 = unpk(acc[r * 2]), v23 = unpk(acc[r * 2 + 1]);
        float v[4] = {v01.x, v01.y, v23.x, v23.y};
        int col = n0 + tx * 4;
        #pragma unroll
        for (int j = 0; j < 4; ++j) {
            float o = v[j];
            if (addb) o += bias[col + j];
            atomicAdd(&C[(size_t)row * N + col + j], o);
        }
    }
}

// ---------------- fused edge pipeline ----------------
__global__ void __launch_bounds__(128) k_edge(
    const float* __restrict__ bbox, const float* __restrict__ dirs,
    const float* __restrict__ pri,
    const float* __restrict__ we1, const float* __restrict__ be1,
    const float* __restrict__ we2, const float* __restrict__ be2,
    const float* __restrict__ we3, const float* __restrict__ be3,
    const float* __restrict__ wp1, const float* __restrict__ bp1,
    const float* __restrict__ Mn, const float* __restrict__ cvec,
    float* __restrict__ out_ea, float* __restrict__ out_agg) {
    __shared__ float s_pair[TE][17];
    __shared__ float s_big[TE * 264];   // h1 [e][256(+8)]
    __shared__ float s_h2[TE][68];
    __shared__ float s_ea[TE][4];
    __shared__ int s_src[TE], s_dst[TE];

    const int t = threadIdx.x;
    const int e0 = blockIdx.x * TE;

    if (t < TE) {
        int e = e0 + t;
        if (e >= NEDGE) e = NEDGE - 1;
        int i = e / 199;
        int r = e - i * 199;
        int j = (r < i) ? r : (r + 1);
        s_src[t] = i; s_dst[t] = j;
    }
    __syncthreads();

    // pair features built directly from bbox/dir (no precomputed attr array)
    #pragma unroll
    for (int l = 0; l < 4; ++l) {
        int q = t + l * 128;
        int el = q >> 4, c = q & 15;
        int node = (c < 8) ? s_src[el] : s_dst[el];
        int cc = c & 7;
        float v = (cc < 4) ? bbox[node * 4 + cc] * (1.0f / 1024.0f)
                           : dirs[node * 4 + (cc - 4)];
        s_pair[el][c] = v;
    }
    __syncthreads();

    const int eg = t >> 4, cg = t & 15;

    // ---- phase 1: L1 16->256 (f32x2): 4 edges x 16 cols per thread
    #pragma unroll
    for (int half = 0; half < 2; ++half) {
        ull acc2[4][4];
        #pragma unroll
        for (int e = 0; e < 4; ++e)
            #pragma unroll
            for (int p = 0; p < 4; ++p) acc2[e][p] = 0ULL;
        #pragma unroll
        for (int j = 0; j < 16; ++j) {
            const ulonglong2* wr = (const ulonglong2*)(we1 + j * 256 + cg * 16 + half * 8);
            ulonglong2 w01 = wr[0], w23 = wr[1];
            #pragma unroll
            for (int e = 0; e < 4; ++e) {
                ull pa = pack2(s_pair[eg * 4 + e][j]);
                ffma2(acc2[e][0], pa, w01.x);
                ffma2(acc2[e][1], pa, w01.y);
                ffma2(acc2[e][2], pa, w23.x);
                ffma2(acc2[e][3], pa, w23.y);
            }
        }
        int colb = cg * 16 + half * 8;
        #pragma unroll
        for (int e = 0; e < 4; ++e) {
            float o[8];
            #pragma unroll
            for (int p = 0; p < 4; ++p) {
                float2 u = unpk(acc2[e][p]);
                o[p * 2] = u.x; o[p * 2 + 1] = u.y;
            }
            #pragma unroll
            for (int c = 0; c < 8; ++c) o[c] = fmaxf(o[c] + be1[colb + c], 0.f);
            float* row = &s_big[(eg * 4 + e) * 264 + colb];
            *(float4*)(row + 0) = make_float4(o[0], o[1], o[2], o[3]);
            *(float4*)(row + 4) = make_float4(o[4], o[5], o[6], o[7]);
        }
    }
    __syncthreads();

    // ---- phase 2: L2 256->64 (f32x2), 2 k's per step via LDS.64 on contiguous k
    {
        ull acc01[4], acc23[4];
        #pragma unroll
        for (int e = 0; e < 4; ++e) { acc01[e] = 0ULL; acc23[e] = 0ULL; }
        #pragma unroll 4
        for (int k = 0; k < 256; k += 2) {
            float2 a0 = *(const float2*)&s_big[(eg * 4 + 0) * 264 + k];
            float2 a1 = *(const float2*)&s_big[(eg * 4 + 1) * 264 + k];
            float2 a2 = *(const float2*)&s_big[(eg * 4 + 2) * 264 + k];
            float2 a3 = *(const float2*)&s_big[(eg * 4 + 3) * 264 + k];
            ulonglong2 b0 = *(const ulonglong2*)(we2 + (k + 0) * 64 + cg * 4);
            ulonglong2 b1 = *(const ulonglong2*)(we2 + (k + 1) * 64 + cg * 4);
            ull p;
            p = pack2(a0.x); ffma2(acc01[0], p, b0.x); ffma2(acc23[0], p, b0.y);
            p = pack2(a1.x); ffma2(acc01[1], p, b0.x); ffma2(acc23[1], p, b0.y);
            p = pack2(a2.x); ffma2(acc01[2], p, b0.x); ffma2(acc23[2], p, b0.y);
            p = pack2(a3.x); ffma2(acc01[3], p, b0.x); ffma2(acc23[3], p, b0.y);
            p = pack2(a0.y); ffma2(acc01[0], p, b1.x); ffma2(acc23[0], p, b1.y);
            p = pack2(a1.y); ffma2(acc01[1], p, b1.x); ffma2(acc23[1], p, b1.y);
            p = pack2(a2.y); ffma2(acc01[2], p, b1.x); ffma2(acc23[2], p, b1.y);
            p = pack2(a3.y); ffma2(acc01[3], p, b1.x); ffma2(acc23[3], p, b1.y);
        }
        #pragma unroll
        for (int e = 0; e < 4; ++e) {
            float2 u0 = unpk(acc01[e]), u1 = unpk(acc23[e]);
            s_h2[eg * 4 + e][cg * 4 + 0] = fmaxf(u0.x + be2[cg * 4 + 0], 0.f);
            s_h2[eg * 4 + e][cg * 4 + 1] = fmaxf(u0.y + be2[cg * 4 + 1], 0.f);
            s_h2[eg * 4 + e][cg * 4 + 2] = fmaxf(u1.x + be2[cg * 4 + 2], 0.f);
            s_h2[eg * 4 + e][cg * 4 + 3] = fmaxf(u1.y + be2[cg * 4 + 3], 0.f);
        }
    }
    __syncthreads();

    // ---- phase 3: L3 64->3 + sigmoid, plus higher-priority bit
    if (t < 96) {
        int e = t / 3, c = t - (t / 3) * 3;
        float s = be3[c];
        #pragma unroll 8
        for (int k = 0; k < 64; ++k) s += s_h2[e][k] * we3[k * 3 + c];
        s_ea[e][c] = 1.f / (1.f + __expf(-s));
    }
    if (t < TE) s_ea[t][3] = (pri[s_src[t]] > pri[s_dst[t]]) ? 1.f : 0.f;
    __syncthreads();

    {   // write edge attributes
        int e = t >> 2, c = t & 3;
        if (e0 + e < NEDGE) out_ea[(size_t)(e0 + e) * 4 + c] = s_ea[e][c];
    }

    // ---- phase 4+5 fused: h in registers, immediate FMA vs M[src], shfl reduce
    {
        int e = t >> 2, q = t & 3;
        int src = s_src[e], dst = s_dst[e];
        float q0 = s_ea[e][0], q1 = s_ea[e][1], q2 = s_ea[e][2], q3 = s_ea[e][3];
        const float4* Mv = (const float4*)(Mn + src * 512);
        float4 a = make_float4(0.f, 0.f, 0.f, 0.f);
        #pragma unroll 8
        for (int kk = 0; kk < 32; ++kk) {
            int k = q * 32 + kk;
            float h = bp1[k] + q0 * wp1[k] + q1 * wp1[128 + k]
                             + q2 * wp1[256 + k] + q3 * wp1[384 + k];
            h = fmaxf(h, 0.f);
            float4 m = Mv[k];
            a.x += h * m.x; a.y += h * m.y; a.z += h * m.z; a.w += h * m.w;
        }
        #pragma unroll
        for (int s = 1; s < 4; s <<= 1) {
            a.x += __shfl_xor_sync(0xffffffffu, a.x, s);
            a.y += __shfl_xor_sync(0xffffffffu, a.y, s);
            a.z += __shfl_xor_sync(0xffffffffu, a.z, s);
            a.w += __shfl_xor_sync(0xffffffffu, a.w, s);
        }
        if (q == 0 && e0 + e < NEDGE) {
            float4 cv = *(const float4*)(cvec + src * 4);
            atomicAdd(&out_agg[dst * 4 + 0], a.x + cv.x);
            atomicAdd(&out_agg[dst * 4 + 1], a.y + cv.y);
            atomicAdd(&out_agg[dst * 4 + 2], a.z + cv.z);
            atomicAdd(&out_agg[dst * 4 + 3], a.w + cv.w);
        }
    }
}

// ---------------- launch ----------------
extern "C" void kernel_launch(void* const* d_in, const int* in_sizes, int n_in,
                              void* d_out, int out_size) {
    const float* roi  = (const float*)d_in[0];
    const float* bbox = (const float*)d_in[1];
    const float* dir  = (const float*)d_in[2];
    const float* pri  = (const float*)d_in[3];
    const float* w1  = (const float*)d_in[4];  const float* b1  = (const float*)d_in[5];
    const float* w2  = (const float*)d_in[6];  const float* b2  = (const float*)d_in[7];
    const float* w3  = (const float*)d_in[8];  const float* b3  = (const float*)d_in[9];
    const float* wi  = (const float*)d_in[10]; const float* bi  = (const float*)d_in[11];
    const float* we1 = (const float*)d_in[12]; const float* be1 = (const float*)d_in[13];
    const float* we2 = (const float*)d_in[14]; const float* be2 = (const float*)d_in[15];
    const float* we3 = (const float*)d_in[16]; const float* be3 = (const float*)d_in[17];
    const float* wp1 = (const float*)d_in[18]; const float* bp1 = (const float*)d_in[19];
    const float* wp2 = (const float*)d_in[20]; const float* bp2 = (const float*)d_in[21];
    const float* rw  = (const float*)d_in[22]; const float* rb  = (const float*)d_in[23];
    float* out = (float*)d_out;

    float* scr;
    cudaGetSymbolAddress((void**)&scr, g_scr);
    float* p_h1 = scr + OFF_H1;
    float* p_h2 = scr + OFF_H2;
    float* p_x  = scr + OFF_X;
    float* p_M  = scr + OFF_M;
    float* p_wt = scr + OFF_WT;
    float* p_c  = scr + OFF_C;

    cudaMemsetAsync(scr, 0, ZERO_CNT * sizeof(float));

    k_tr<<<(128 * 1024) / 256, 256>>>(wp2, p_wt);

    // node MLP (batch 0 only), deep split-K to fill the chip
    sgemm_sk<0><<<dim3(4, 7, 16), 256>>>(roi,  w1, b1, p_h1, NNODE, HD1, IMGF, 128);
    sgemm_sk<1><<<dim3(2, 7, 16), 256>>>(p_h1, w2, b2, p_h2, NNODE, HD2, HD1,  32);
    sgemm_sk<1><<<dim3(8, 7, 8),  256>>>(p_h2, w3, b3, p_x,  NNODE, NCH, HD2,  32);

    // M[n, k*4+o] = x @ wp2t
    sgemm_sk<0><<<dim3(4, 7, 16), 256>>>(p_x, p_wt, (const float*)nullptr, p_M,
                                         NNODE, 512, NCH, 64);

    k_vec4b<<<NNODE, 256>>>(p_x, wi, bi, bp2, rw, rb, out + 800, p_c, out);

    k_edge<<<(NEDGE + TE - 1) / TE, 128>>>(bbox, dir, pri,
                                           we1, be1, we2, be2, we3, be3,
                                           wp1, bp1, p_M, p_c,
                                           out + 1600, out);
}